// round 12
// baseline (speedup 1.0000x reference)
#include <cuda_runtime.h>
#include <cstdint>

#define NPTS 8192
#define KNN  8

typedef unsigned long long u64t;

__device__ __forceinline__ u64t pk2(float x) {
    u64t r; asm("mov.b64 %0, {%1, %1};" : "=l"(r) : "f"(x)); return r;
}
__device__ __forceinline__ u64t f2fma(u64t a, u64t b, u64t c) {
    u64t d; asm("fma.rn.f32x2 %0, %1, %2, %3;" : "=l"(d) : "l"(a), "l"(b), "l"(c)); return d;
}
__device__ __forceinline__ float2 up2(u64t v) {
    float2 f; asm("mov.b64 {%0, %1}, %2;" : "=f"(f.x), "=f"(f.y) : "l"(v)); return f;
}
__device__ __forceinline__ void cpa16(float* dst, const float* src) {
    uint32_t d = (uint32_t)__cvta_generic_to_shared(dst);
    asm volatile("cp.async.ca.shared.global [%0], [%1], 16;\n" :: "r"(d), "l"(src));
}
__device__ __forceinline__ void cpa4(int* dst, const int* src) {
    uint32_t d = (uint32_t)__cvta_generic_to_shared(dst);
    asm volatile("cp.async.ca.shared.global [%0], [%1], 4;\n" :: "r"(d), "l"(src));
}
#define CPA_COMMIT asm volatile("cp.async.commit_group;\n" ::: "memory")
#define CPA_WAIT0  asm volatile("cp.async.wait_group 0;\n" ::: "memory")

// ---------------- scratch ----------------
__device__ __align__(16) float4 g_pts4[NPTS];
__device__ int                  g_idx[NPTS * KNN];
__device__ __align__(16) float  g_qp1[NPTS * 128];
__device__ __align__(16) float  g_x1 [NPTS * 128];
__device__ __align__(16) float  g_qp2[NPTS * 256];
__device__ __align__(16) float  g_wcat[128 * 256];

// ---------------- prep ----------------
__global__ void k_prep(const float* __restrict__ pc) {
    int i = blockIdx.x * blockDim.x + threadIdx.x;
    if (i < NPTS) {
        float x = pc[3*i], y = pc[3*i+1], z = pc[3*i+2];
        float s = fmaf(x, x, fmaf(y, y, z*z));
        g_pts4[i] = make_float4(x, y, z, s);
    }
}

// ---------------- KNN (R5/R11 shape) ----------------
__global__ void k_knn() {
    extern __shared__ char sm[];
    float4* sp = (float4*)sm;
    float*  md = (float*)(sm + NPTS * 16);
    int*    mi = (int*)  (sm + NPTS * 16 + 64 * 33 * 4);

    int tid = threadIdx.x;
    for (int t = tid; t < NPTS; t += 256) sp[t] = g_pts4[t];
    __syncthreads();

    int part = tid >> 6;
    int lp   = tid & 63;
    int pt   = blockIdx.x * 64 + lp;
    float4 me = sp[pt];

    float bd[8]; int bj[8];
#pragma unroll
    for (int s = 0; s < 8; s++) { bd[s] = 3.4e38f; bj[s] = 0x7fffffff; }

    int j0 = part * 2048;
#pragma unroll 4
    for (int jj = 0; jj < 2048; jj++) {
        int j = j0 + jj;
        float4 o = sp[j];
        float dot = fmaf(me.x, o.x, fmaf(me.y, o.y, me.z * o.z));
        float d   = fmaf(-2.0f, dot, me.w + o.w);
        if (d < bd[7]) {
            bd[7] = d; bj[7] = j;
#pragma unroll
            for (int s = 7; s > 0; s--) {
                if (bd[s] < bd[s-1]) {
                    float td = bd[s]; bd[s] = bd[s-1]; bd[s-1] = td;
                    int   tj = bj[s]; bj[s] = bj[s-1]; bj[s-1] = tj;
                }
            }
        }
    }
#pragma unroll
    for (int s = 0; s < 8; s++) {
        md[lp * 33 + part * 8 + s] = bd[s];
        mi[lp * 33 + part * 8 + s] = bj[s];
    }
    __syncthreads();

    if (tid < 64) {
        float* rd = md + tid * 33;
        int*   ri = mi + tid * 33;
        int po = (blockIdx.x * 64 + tid) * KNN;
        for (int s = 0; s < 8; s++) {
            float bdd = 3.4e38f; int bjj = 0x7fffffff; int bp = 0;
            for (int t = 0; t < 32; t++) {
                float dd = rd[t]; int jj = ri[t];
                if (dd < bdd || (dd == bdd && jj < bjj)) { bdd = dd; bjj = jj; bp = t; }
            }
            rd[bp] = 3.4e38f;
            g_idx[po + s] = bjj;
        }
    }
}

// ---------------- P1 ----------------
__global__ void k_lin1(const float* __restrict__ W1, const float* __restrict__ pc) {
    int g = blockIdx.x * blockDim.x + threadIdx.x;
    if (g >= NPTS * 32) return;
    int i = g >> 5, q = g & 31;
    float x0 = pc[3*i], x1 = pc[3*i+1], x2 = pc[3*i+2];
    bool isQ = (q < 16);
    int c = (isQ ? q : q - 16) * 4;
    float v[4];
#pragma unroll
    for (int u = 0; u < 4; u++) {
        float wa0 = W1[0*64 + c+u], wa1 = W1[1*64 + c+u], wa2 = W1[2*64 + c+u];
        float wb0 = W1[3*64 + c+u], wb1 = W1[4*64 + c+u], wb2 = W1[5*64 + c+u];
        if (isQ) v[u] = x0*(wa0-wb0) + x1*(wa1-wb1) + x2*(wa2-wb2);
        else     v[u] = x0*wb0 + x1*wb1 + x2*wb2;
    }
    *(float4*)&g_qp1[i * 128 + q * 4] = make_float4(v[0], v[1], v[2], v[3]);
}

// ---------------- Wcat ----------------
__global__ void k_wcat(const float* __restrict__ W3) {
    int g = blockIdx.x * blockDim.x + threadIdx.x;
    if (g >= 128 * 256) return;
    int m = g >> 8, n = g & 255;
    float v;
    if (n < 128) v = W3[m * 128 + n] - W3[(m + 128) * 128 + n];
    else         v = W3[(m + 128) * 128 + (n - 128)];
    g_wcat[m * 256 + n] = v;
}

// ---------------- mainloop segment (R11 inner loop) ----------------
template<int N>
__device__ __forceinline__ void seg_compute(const float* __restrict__ A0,
                                            const float* __restrict__ W0,
                                            int tm, int tn, u64t acc2[4][4]) {
#pragma unroll 4
    for (int c = 0; c < N; c++) {
        ulonglong2 av0 = *(const ulonglong2*)&A0[c * 64 + tm * 8];
        ulonglong2 av1 = *(const ulonglong2*)&A0[c * 64 + tm * 8 + 4];
        u64t ap[4] = {av0.x, av0.y, av1.x, av1.y};
        float4 w = *(const float4*)&W0[c * 128 + tn * 4];
        u64t wd[4] = {pk2(w.x), pk2(w.y), pk2(w.z), pk2(w.w)};
#pragma unroll
        for (int p = 0; p < 4; p++)
#pragma unroll
            for (int n = 0; n < 4; n++)
                acc2[p][n] = f2fma(ap[p], wd[n], acc2[p][n]);
    }
}

// ---------------- pipelined edge GEMM ----------------
// Block handles T row-tiles of 64 edge-rows. cp.async prefetches tile t+1's
// neighbor rows (praw) + query rows (qraw) during tile t's FMA loop; combine
// (relu(q+p+b), transpose into As) is smem->smem. idx prefetched one tile ahead.
// WRES: W N-tile resident (EC1). else: W loaded in 2 KC-chunks per tile (EC2).
template<int KDIM, int KC, int T, bool WRES, bool RELU_OUT, int NOUT>
__global__ void __launch_bounds__(256, 2) k_edge(
    const float* __restrict__ qA, const float* __restrict__ pB, int qstride,
    const float* __restrict__ bK, const float* __restrict__ Wg,
    const float* __restrict__ bN, float* __restrict__ out)
{
    const int PKD = KDIM + 4;          // praw row pitch (floats, 16B multiple)
    const int CH  = KDIM / 4;          // 16B chunks per row
    extern __shared__ float smf[];
    float* As   = smf;                                  // [KDIM][64]
    float* Ws   = As + KDIM * 64;                       // [WRES?KDIM:KC][128]
    float* praw = Ws + (WRES ? KDIM : KC) * 128;        // [64][PKD]
    float* qraw = praw + 64 * PKD;                      // [8][KDIM]
    float* bb   = qraw + 8 * KDIM;                      // [KDIM]
    int*   sidx = (int*)(bb + KDIM);                    // [64]

    int tid = threadIdx.x;
    int nt0 = blockIdx.y * 128;
    int tile0 = blockIdx.x * T;
    int tm = tid >> 5, tn = tid & 31;

    for (int t = tid; t < KDIM; t += 256) bb[t] = bK[t];
    if (WRES) {
        float4* Ws4 = (float4*)Ws; const float4* Wg4 = (const float4*)Wg;
#pragma unroll 4
        for (int t = tid; t < KDIM * 32; t += 256)
            Ws4[t] = Wg4[((t >> 5) * NOUT + nt0) / 4 + (t & 31)];
    }

    auto issue_idx = [&](int tile) {
        if (tid < 64) cpa4(&sidx[tid], &g_idx[tile * 64 + tid]);
    };
    auto issue_gather = [&](int tile) {
#pragma unroll
        for (int k = 0; k < 64 * CH / 256; k++) {
            int task = tid + k * 256;
            int rr = task / CH, c4 = task % CH;
            int j = sidx[rr];
            cpa16(&praw[rr * PKD + c4 * 4], &pB[(long)j * qstride + c4 * 4]);
        }
        if (tid < 8 * CH) {
            int rr = tid / CH, c4 = tid % CH;
            cpa16(&qraw[rr * KDIM + c4 * 4], &qA[(long)(tile * 8 + rr) * qstride + c4 * 4]);
        }
    };
    auto combine = [&]() {
#pragma unroll
        for (int k = 0; k < 64 * CH / 256; k++) {
            int task = tid + k * 256;
            int rr = task & 63, c4 = task >> 6;
            float4 p = *(const float4*)&praw[rr * PKD + c4 * 4];
            float4 q = *(const float4*)&qraw[(rr >> 3) * KDIM + c4 * 4];
            float4 b = *(const float4*)&bb[c4 * 4];
            As[(c4*4 + 0) * 64 + rr] = fmaxf(q.x + p.x + b.x, 0.0f);
            As[(c4*4 + 1) * 64 + rr] = fmaxf(q.y + p.y + b.y, 0.0f);
            As[(c4*4 + 2) * 64 + rr] = fmaxf(q.z + p.z + b.z, 0.0f);
            As[(c4*4 + 3) * 64 + rr] = fmaxf(q.w + p.w + b.w, 0.0f);
        }
    };
    auto loadW = [&](int chunk) {
        float4* Ws4 = (float4*)Ws; const float4* Wg4 = (const float4*)Wg;
#pragma unroll 4
        for (int t = tid; t < KC * 32; t += 256)
            Ws4[t] = Wg4[((chunk * KC + (t >> 5)) * NOUT + nt0) / 4 + (t & 31)];
    };

    // prologue: tile0 fully fetched + combined (exposed once per block)
    issue_idx(tile0); CPA_COMMIT;
    CPA_WAIT0; __syncthreads();
    issue_gather(tile0); CPA_COMMIT;
    CPA_WAIT0; __syncthreads();
    combine();
    if (T > 1) { issue_idx(tile0 + 1); CPA_COMMIT; }
    __syncthreads();

    for (int t = 0; t < T; t++) {
        int tile = tile0 + t;
        u64t acc2[4][4];
#pragma unroll
        for (int p = 0; p < 4; p++)
#pragma unroll
            for (int n = 0; n < 4; n++) acc2[p][n] = 0ull;

        if (WRES) {
            seg_compute<KDIM/2>(As, Ws, tm, tn, acc2);
            if (t + 1 < T) { CPA_WAIT0; __syncthreads(); issue_gather(tile + 1); CPA_COMMIT; }
            seg_compute<KDIM/2>(As + (KDIM/2) * 64, Ws + (KDIM/2) * 128, tm, tn, acc2);
        } else {
            __syncthreads(); loadW(0); __syncthreads();
            seg_compute<KC>(As, Ws, tm, tn, acc2);
            if (t + 1 < T) { CPA_WAIT0; __syncthreads(); issue_gather(tile + 1); CPA_COMMIT; }
            __syncthreads(); loadW(1); __syncthreads();
            seg_compute<KC>(As + KC * 64, Ws, tm, tn, acc2);
        }

        // epilogue: max over the point's 8 edge-rows (register-local per warp-row)
        {
            int pt = tile * 8 + tm;
            float res[4];
#pragma unroll
            for (int n = 0; n < 4; n++) {
                float2 v0 = up2(acc2[0][n]);
                float2 v1 = up2(acc2[1][n]);
                float2 v2 = up2(acc2[2][n]);
                float2 v3 = up2(acc2[3][n]);
                float m = fmaxf(fmaxf(fmaxf(v0.x, v0.y), fmaxf(v1.x, v1.y)),
                                fmaxf(fmaxf(v2.x, v2.y), fmaxf(v3.x, v3.y)));
                m += bN[nt0 + tn * 4 + n];
                if (RELU_OUT) m = fmaxf(m, 0.0f);
                res[n] = m;
            }
            *(float4*)&out[(long)pt * NOUT + nt0 + tn * 4] =
                make_float4(res[0], res[1], res[2], res[3]);
        }

        if (t + 1 < T) {
            CPA_WAIT0; __syncthreads();
            combine();
            if (t + 2 < T) { issue_idx(tile + 2); CPA_COMMIT; }
            __syncthreads();
        }
    }
}

// ---------------- plain GEMM (P2, R11 shape) ----------------
template<int KDIM, int KC, int NOUT>
__global__ void __launch_bounds__(256) k_plain(
    const float* __restrict__ qA, int qstride,
    const float* __restrict__ Wg, float* __restrict__ out)
{
    extern __shared__ float smf[];
    float* As = smf;
    float* Ws = smf + KDIM * 64;
    int tid = threadIdx.x;
    int blk = blockIdx.x;
    int nt0 = blockIdx.y * 128;

    {
        const int TASKS = 64 * (KDIM / 4);
        int base64 = blk * 64;
        for (int t = tid; t < TASKS; t += 256) {
            int rr = t & 63, c4 = t >> 6;
            float4 v = *(const float4*)&qA[(long)(base64 + rr) * qstride + c4 * 4];
            As[(c4*4 + 0) * 64 + rr] = v.x;
            As[(c4*4 + 1) * 64 + rr] = v.y;
            As[(c4*4 + 2) * 64 + rr] = v.z;
            As[(c4*4 + 3) * 64 + rr] = v.w;
        }
    }

    int tm = tid >> 5, tn = tid & 31;
    u64t acc2[4][4];
#pragma unroll
    for (int p = 0; p < 4; p++)
#pragma unroll
        for (int n = 0; n < 4; n++) acc2[p][n] = 0ull;

    const float4* Wg4 = (const float4*)Wg;
    for (int kc = 0; kc < KDIM / KC; kc++) {
        __syncthreads();
        {
            float4* Ws4 = (float4*)Ws;
#pragma unroll 4
            for (int t = tid; t < KC * 32; t += 256)
                Ws4[t] = Wg4[((kc * KC + (t >> 5)) * NOUT + nt0) / 4 + (t & 31)];
        }
        __syncthreads();
        seg_compute<KC>(As + kc * KC * 64, Ws, tm, tn, acc2);
    }

    int base = blk * 64;
#pragma unroll
    for (int p = 0; p < 4; p++) {
        float2 c0 = up2(acc2[p][0]);
        float2 c1 = up2(acc2[p][1]);
        float2 c2 = up2(acc2[p][2]);
        float2 c3 = up2(acc2[p][3]);
        int row0 = base + tm * 8 + 2 * p;
        *(float4*)&out[(long)row0 * NOUT + nt0 + tn * 4] =
            make_float4(c0.x, c1.x, c2.x, c3.x);
        *(float4*)&out[(long)(row0 + 1) * NOUT + nt0 + tn * 4] =
            make_float4(c0.y, c1.y, c2.y, c3.y);
    }
}

// ---------------- launch ----------------
extern "C" void kernel_launch(void* const* d_in, const int* in_sizes, int n_in,
                              void* d_out, int out_size) {
    const float* pc = (const float*)d_in[0];
    const float* W1 = (const float*)d_in[1];
    const float* b1 = (const float*)d_in[2];
    const float* W2 = (const float*)d_in[3];
    const float* b2 = (const float*)d_in[4];
    const float* W3 = (const float*)d_in[5];
    const float* b3 = (const float*)d_in[6];
    const float* W4 = (const float*)d_in[7];
    const float* b4 = (const float*)d_in[8];
    float* out = (float*)d_out;

    float *qp1 = nullptr, *x1 = nullptr, *qp2 = nullptr, *wcat = nullptr;
    cudaGetSymbolAddress((void**)&qp1,  g_qp1);
    cudaGetSymbolAddress((void**)&x1,   g_x1);
    cudaGetSymbolAddress((void**)&qp2,  g_qp2);
    cudaGetSymbolAddress((void**)&wcat, g_wcat);

    const int SM_KNN = NPTS * 16 + 2 * 64 * 33 * 4;
    // EC1: As 16K + W 32K + praw 64*68*4 + qraw 2K + bb 256 + idx 256
    const int SM_E1 = (64*64 + 64*128 + 64*68 + 8*64 + 64) * 4 + 256;
    // EC2: As 32K + Wchunk 32K + praw 64*132*4 + qraw 4K + bb 512 + idx 256
    const int SM_E2 = (128*64 + 64*128 + 64*132 + 8*128 + 128) * 4 + 256;
    const int SM_P2 = (128 * 64 + 64 * 128) * 4;

    cudaFuncSetAttribute(k_knn, cudaFuncAttributeMaxDynamicSharedMemorySize, SM_KNN);
    cudaFuncSetAttribute((const void*)k_edge<64,64,2,true,true,128>,
                         cudaFuncAttributeMaxDynamicSharedMemorySize, SM_E1);
    cudaFuncSetAttribute((const void*)k_edge<128,64,8,false,false,256>,
                         cudaFuncAttributeMaxDynamicSharedMemorySize, SM_E2);
    cudaFuncSetAttribute((const void*)k_plain<128,64,256>,
                         cudaFuncAttributeMaxDynamicSharedMemorySize, SM_P2);

    // 1. pack points
    k_prep<<<(NPTS + 255) / 256, 256>>>(pc);
    // 2. knn
    k_knn<<<NPTS / 64, 256, SM_KNN>>>();
    // 3. per-point linear factors for EdgeConv1
    k_lin1<<<(NPTS * 32 + 255) / 256, 256>>>(W1, pc);
    // 4. EdgeConv1: pipelined edge GEMM (K=64 -> N=128) + max + relu -> x1
    //    tiles = 1024, T=2 -> 512 blocks
    k_edge<64,64,2,true,true,128><<<dim3(NPTS * KNN / 64 / 2, 1), 256, SM_E1>>>(
        qp1, qp1 + 64, 128, b1, W2, b2, x1);
    // 5. Wcat
    k_wcat<<<(128 * 256 + 255) / 256, 256>>>(W3);
    // 6. P2: x1 @ Wcat -> qA2|pB2
    k_plain<128,64,256><<<dim3(NPTS / 64, 2), 256, SM_P2>>>(x1, 128, wcat, qp2);
    // 7. EdgeConv2: pipelined edge GEMM (K=128 -> N=256) + max -> out
    //    tiles = 1024 per N-tile, T=8 -> 128 blocks x 2
    k_edge<128,64,8,false,false,256><<<dim3(NPTS * KNN / 64 / 8, 2), 256, SM_E2>>>(
        qp2, qp2 + 128, 256, b3, W4, b4, out);
}